// round 7
// baseline (speedup 1.0000x reference)
#include <cuda_runtime.h>
#include <cuda_fp16.h>
#include <math.h>

#define Lc 37
#define Kc 8
#define HMc 512
#define HSc 128
#define HCc 64
#define Bc 2
#define NIMGP (Lc*Kc)     // 296
#define NBL   (Bc*Lc)     // 74
#define NFFT 256

// ---------------- device scratch ----------------
__device__ float   g_tmpA[NBL*HMc*HSc];
__device__ float   g_hmrs[NBL*HSc*HSc];
__device__ float   g_prior[NIMGP*HSc*HSc];
__device__ __half2 g_RL[NIMGP*HSc*NFFT];    // like row spectra (b0+i*b1), fp16
__device__ __half2 g_RP[NIMGP*HSc*NFFT];    // prior row spectra, fp16
__device__ __half2 g_TL[NIMGP*HSc*NFFT];    // col-conv result (scaled 1/65536), fp16
__device__ float   g_energy128[NBL*HSc*HSc];
__device__ float2  g_rowbn[NBL*HMc];
__device__ float   g_scale[Lc], g_bofs[Lc];
__device__ float4  g_rs[NBL*HMc];
__device__ float2  g_twf[128];              // (cos,sin) of -2*pi*e/256
__device__ float   g_wDT[16][HSc];
__device__ float   g_wU64T[4][HSc];
__device__ int     g_wU64s[HSc];
__device__ float   g_wU128T[4][HMc];
__device__ int     g_wU128s[HMc];

// ---------------- helpers ----------------
__device__ __forceinline__ float2 cmulf(float2 a, float2 b){
  return make_float2(fmaf(a.x,b.x,-a.y*b.y), fmaf(a.x,b.y,a.y*b.x));
}
__device__ __forceinline__ float2 cadd(float2 a, float2 b){ return make_float2(a.x+b.x, a.y+b.y); }
__device__ __forceinline__ float2 csub(float2 a, float2 b){ return make_float2(a.x-b.x, a.y-b.y); }
__device__ __forceinline__ float2 tw(int e, float sgn){
  float2 w = g_twf[e];
  return make_float2(w.x, w.y*sgn);
}
__device__ __forceinline__ float2 shx2(float2 v, int m){
  return make_float2(__shfl_xor_sync(0xffffffffu, v.x, m),
                     __shfl_xor_sync(0xffffffffu, v.y, m));
}
__device__ __forceinline__ float spb(float x){
  float t = 5.f*x;
  return 0.2f*(fmaxf(t,0.f) + log1pf(__expf(-fabsf(t))));
}
__device__ double keysd(double x){
  if (x >= 2.0) return 0.0;
  if (x >= 1.0) return ((-0.5*x + 2.5)*x - 4.0)*x + 2.0;
  return ((1.5*x - 2.5)*x)*x + 1.0;
}
__device__ __forceinline__ __half2 pack(float2 v){ return __floats2half2_rn(v.x, v.y); }
__device__ __forceinline__ float2 unpack(__half2 h){ float2 v = __half22float2(h); return v; }

__device__ __forceinline__ void fft_fwd(float2 v[8], int t){
#pragma unroll
  for (int j=0;j<4;j++){
    float2 a=v[j], b=v[j+4];
    v[j]=cadd(a,b);
    v[j+4]=cmulf(csub(a,b), tw(j*32+t, 1.f));
  }
#pragma unroll
  for (int g=0; g<8; g+=4){
#pragma unroll
    for (int j2=0;j2<2;j2++){
      int jl=g+j2, jh=g+j2+2;
      float2 a=v[jl], b=v[jh];
      v[jl]=cadd(a,b);
      v[jh]=cmulf(csub(a,b), tw(((j2*32+t)*2)&127, 1.f));
    }
  }
  {
    float2 w = tw((t*4)&127, 1.f);
#pragma unroll
    for (int p=0;p<8;p+=2){
      float2 a=v[p], b=v[p+1];
      v[p]=cadd(a,b);
      v[p+1]=cmulf(csub(a,b), w);
    }
  }
#pragma unroll
  for (int hs=4; hs>=0; hs--){
    int h = 1<<hs;
    float2 w = tw((t & (h-1)) * (128>>hs), 1.f);
    bool up = (t & h) != 0;
#pragma unroll
    for (int j=0;j<8;j++){
      float2 o = shx2(v[j], h);
      v[j] = up ? cmulf(csub(o, v[j]), w) : cadd(v[j], o);
    }
  }
}
__device__ __forceinline__ void fft_inv(float2 v[8], int t){
#pragma unroll
  for (int hs=0; hs<=4; hs++){
    int h = 1<<hs;
    float2 w = tw((t & (h-1)) * (128>>hs), -1.f);
    bool up = (t & h) != 0;
#pragma unroll
    for (int j=0;j<8;j++){
      float2 o = shx2(v[j], h);
      v[j] = up ? csub(o, cmulf(v[j], w)) : cadd(v[j], cmulf(o, w));
    }
  }
  {
    float2 w = tw((t*4)&127, -1.f);
#pragma unroll
    for (int p=0;p<8;p+=2){
      float2 a=v[p];
      float2 wb=cmulf(v[p+1], w);
      v[p]=cadd(a,wb); v[p+1]=csub(a,wb);
    }
  }
#pragma unroll
  for (int g=0; g<8; g+=4){
#pragma unroll
    for (int j2=0;j2<2;j2++){
      int jl=g+j2, jh=g+j2+2;
      float2 a=v[jl];
      float2 wb=cmulf(v[jh], tw(((j2*32+t)*2)&127, -1.f));
      v[jl]=cadd(a,wb); v[jh]=csub(a,wb);
    }
  }
#pragma unroll
  for (int j=0;j<4;j++){
    float2 a=v[j];
    float2 wb=cmulf(v[j+4], tw(j*32+t, -1.f));
    v[j]=cadd(a,wb); v[j+4]=csub(a,wb);
  }
}

__device__ __forceinline__ float bredmax(float v, float* sh16){
#pragma unroll
  for (int m=16;m;m>>=1) v = fmaxf(v, __shfl_xor_sync(0xffffffffu, v, m));
  if (!(threadIdx.x&31)) sh16[threadIdx.x>>5]=v;
  __syncthreads();
  float r = sh16[0];
#pragma unroll
  for (int i=1;i<16;i++) r = fmaxf(r, sh16[i]);
  __syncthreads();
  return r;
}
__device__ __forceinline__ float bredsum(float v, float* sh16){
#pragma unroll
  for (int m=16;m;m>>=1) v += __shfl_xor_sync(0xffffffffu, v, m);
  if (!(threadIdx.x&31)) sh16[threadIdx.x>>5]=v;
  __syncthreads();
  float r = 0.f;
#pragma unroll
  for (int i=0;i<16;i++) r += sh16[i];
  __syncthreads();
  return r;
}

// ---------------- setup ----------------
__global__ void k_setup(){
  int t = threadIdx.x;
  if (t < 128){
    double sv,cv; sincospi(-(double)t/128.0, &sv, &cv);
    g_twf[t] = make_float2((float)cv,(float)sv);
  }
  if (t < HSc){
    double sf = 4.0*t + 1.5;
    int s0 = 4*t - 6;
    double w[16], ws=0.0;
    for (int j=0;j<16;j++){
      int i=s0+j;
      double kv = keysd(fabs(sf-(double)i)*0.25);
      if (i<0 || i>511) kv=0.0;
      w[j]=kv; ws+=kv;
    }
    for (int j=0;j<16;j++) g_wDT[j][t]=(float)(w[j]/ws);
    double sf2 = 0.5*t - 0.25;
    int b0 = (int)floor(sf2)-1;
    g_wU64s[t]=b0;
    double w4[4]; ws=0.0;
    for (int j=0;j<4;j++){
      int i=b0+j;
      double kv = keysd(fabs(sf2-(double)i));
      if (i<0||i>63) kv=0.0;
      w4[j]=kv; ws+=kv;
    }
    for (int j=0;j<4;j++) g_wU64T[j][t]=(float)(w4[j]/ws);
  }
  if (t < HMc){
    double sf = 0.25*t - 0.375;
    int b0 = (int)floor(sf)-1;
    g_wU128s[t]=b0;
    double w4[4], ws=0.0;
    for (int j=0;j<4;j++){
      int i=b0+j;
      double kv = keysd(fabs(sf-(double)i));
      if (i<0||i>127) kv=0.0;
      w4[j]=kv; ws+=kv;
    }
    for (int j=0;j<4;j++) g_wU128T[j][t]=(float)(w4[j]/ws);
  }
}

// ---------------- resize x-pass + BN partials ----------------
__global__ void k_r1(const float* __restrict__ heat){
  int row = blockIdx.x;          // bl*512+y
  const float* src = heat + (size_t)row*HMc;
  int oc = threadIdx.x;
  const float4* s4 = (const float4*)src;
  float acc=0.f;
  float4 own;
  if (oc>=2 && oc<126){
    float x[20];
#pragma unroll
    for (int d=0; d<5; d++){
      float4 f = s4[oc-2+d];
      x[4*d]=f.x; x[4*d+1]=f.y; x[4*d+2]=f.z; x[4*d+3]=f.w;
    }
    own = make_float4(x[8],x[9],x[10],x[11]);
#pragma unroll
    for (int j=0;j<16;j++) acc = fmaf(g_wDT[j][oc], x[2+j], acc);
  } else {
    int s0 = 4*oc-6;
#pragma unroll
    for (int j=0;j<16;j++){
      int i = min(max(s0+j,0),HMc-1);
      acc = fmaf(g_wDT[j][oc], src[i], acc);
    }
    own = s4[oc];
  }
  g_tmpA[(size_t)row*HSc+oc] = acc;
  float s = own.x+own.y+own.z+own.w;
  float ss = fmaf(own.x,own.x, fmaf(own.y,own.y, fmaf(own.z,own.z, own.w*own.w)));
#pragma unroll
  for (int m=16;m;m>>=1){
    s  += __shfl_xor_sync(0xffffffffu, s, m);
    ss += __shfl_xor_sync(0xffffffffu, ss, m);
  }
  __shared__ float2 sw[4];
  if (!(oc&31)) sw[oc>>5]=make_float2(s,ss);
  __syncthreads();
  if (!oc){
    float2 a=sw[0],b=sw[1],c=sw[2],d=sw[3];
    g_rowbn[row]=make_float2(a.x+b.x+c.x+d.x, a.y+b.y+c.y+d.y);
  }
}
__global__ void k_bn_final(const float* __restrict__ gamma, const float* __restrict__ beta){
  int l = blockIdx.x, t = threadIdx.x;  // 256
  float s=0.f, ss=0.f;
  for (int i=t;i<1024;i+=256){
    int row = ((i<512)? l : (Lc+l))*HMc + (i&511);
    float2 v = g_rowbn[row];
    s+=v.x; ss+=v.y;
  }
#pragma unroll
  for (int m=16;m;m>>=1){ s += __shfl_xor_sync(0xffffffffu,s,m); ss += __shfl_xor_sync(0xffffffffu,ss,m); }
  __shared__ float2 sw[8];
  if (!(t&31)) sw[t>>5]=make_float2(s,ss);
  __syncthreads();
  if (!t){
    float S=0.f,SS=0.f;
#pragma unroll
    for (int i=0;i<8;i++){ S+=sw[i].x; SS+=sw[i].y; }
    const float N=524288.f;
    float mean=S/N, var=SS/N-mean*mean;
    float sc = gamma[l]*rsqrtf(var+1e-5f);
    g_scale[l]=sc;
    g_bofs[l]=beta[l]-mean*sc;
  }
}
__global__ void k_r2(){
  int orow = blockIdx.x;         // bl*128+oy
  int bl = orow>>7, oy = orow&127;
  int oc = threadIdx.x;
  int s0 = 4*oy-6;
  float acc=0.f;
#pragma unroll
  for (int j=0;j<16;j++){
    int i = min(max(s0+j,0),HMc-1);
    acc = fmaf(g_wDT[j][oy], g_tmpA[((size_t)bl*HMc+i)*HSc+oc], acc);
  }
  g_hmrs[(size_t)orow*HSc+oc] = acc;
}

// ---------------- prior ----------------
__global__ void k_prior(const float* __restrict__ cond){
  int orow = blockIdx.x;
  int lk = orow>>7, oy = orow&127;
  int ox = threadIdx.x;
  int sy=g_wU64s[oy], sx=g_wU64s[ox];
  const float* src = cond + (size_t)lk*HCc*HCc;
  float wx[4];
#pragma unroll
  for (int j=0;j<4;j++) wx[j]=g_wU64T[j][ox];
  float acc=0.f;
#pragma unroll
  for (int a=0;a<4;a++){
    int iy = min(max(sy+a,0),HCc-1);
    float r=0.f;
#pragma unroll
    for (int b2=0;b2<4;b2++){
      int ix = min(max(sx+b2,0),HCc-1);
      r = fmaf(wx[b2], src[iy*HCc+ix], r);
    }
    acc = fmaf(g_wU64T[a][oy], r, acc);
  }
  g_prior[(size_t)orow*HSc+ox] = spb(acc);
}

// ---------------- row FFTs: blockIdx.y 0=prior, 1=like ----------------
__global__ void k_rows(const int* __restrict__ vidx){
  int gw = blockIdx.x*8 + (threadIdx.x>>5);  // lk*128+row
  int t = threadIdx.x & 31;
  float2 v[8];
  if (blockIdx.y==0){
    const float* src = g_prior + (size_t)gw*HSc;
#pragma unroll
    for (int j=0;j<8;j++) v[j] = (j<4)? make_float2(src[j*32+t],0.f) : make_float2(0.f,0.f);
  } else {
    int lk = gw>>7, row = gw&127;
    int c = vidx[lk];
    float sc = g_scale[c], bo = g_bofs[c];
    const float* s0 = g_hmrs + (((size_t)c)*HSc+row)*HSc;
    const float* s1 = g_hmrs + (((size_t)(Lc+c))*HSc+row)*HSc;
#pragma unroll
    for (int j=0;j<8;j++){
      if (j<4){
        int x=j*32+t;
        v[j]=make_float2(spb(fmaf(s0[x],sc,bo)), spb(fmaf(s1[x],sc,bo)));
      } else v[j]=make_float2(0.f,0.f);
    }
  }
  fft_fwd(v,t);
  __half2* dst = (blockIdx.y==0 ? g_RP : g_RL) + (size_t)gw*NFFT;
#pragma unroll
  for (int j=0;j<8;j++) dst[j*32+t]=pack(v[j]);
}

// ---------------- columns: likeFFT x priorFFT -> inverse ----------------
__global__ void k_cols_conv(){
  __shared__ float2 tl[128][9];
  __shared__ float2 tp[128][9];
  int kx0 = blockIdx.x*8;
  int lk = blockIdx.y;
  int tid = threadIdx.x;
  const __half2* srcL = g_RL + (size_t)lk*HSc*NFFT;
  const __half2* srcP = g_RP + (size_t)lk*HSc*NFFT;
  for (int i=tid;i<1024;i+=256){
    int r=i>>3, c=i&7;
    tl[r][c]=unpack(__ldcs(&srcL[r*NFFT + kx0 + c]));
    tp[r][c]=unpack(__ldcs(&srcP[r*NFFT + kx0 + c]));
  }
  __syncthreads();
  int w = tid>>5, t = tid&31;
  float2 vp[8], v[8];
#pragma unroll
  for (int j=0;j<8;j++){
    vp[j] = (j<4)? tp[j*32+t][w] : make_float2(0.f,0.f);
    v[j]  = (j<4)? tl[j*32+t][w] : make_float2(0.f,0.f);
  }
  fft_fwd(vp,t);
  fft_fwd(v,t);
  const float sc = 1.f/65536.f;
#pragma unroll
  for (int j=0;j<8;j++){
    v[j]=cmulf(v[j], vp[j]);
    v[j]=make_float2(v[j].x*sc, v[j].y*sc);
  }
  fft_inv(v,t);
#pragma unroll
  for (int j=2;j<6;j++) tl[(j-2)*32+t][w]=v[j];
  __syncthreads();
  __half2* dst = g_TL + (size_t)lk*HSc*NFFT;
  for (int i=tid;i<1024;i+=256){
    int r=i>>3, c=i&7;
    dst[r*NFFT + kx0 + c]=pack(tl[r][c]);
  }
}

// ---------------- inverse row FFT + log-energy over K ----------------
__global__ void k_energy(const float* __restrict__ bias){
  __shared__ float sm0[8][128], sm1[8][128];
  int ly = blockIdx.x;             // l*128+y
  int y = ly&127, l = ly>>7;
  int tid = threadIdx.x;
  int k = tid>>5, t = tid&31;
  int lk = l*Kc + k;
  const __half2* src = g_TL + ((size_t)lk*HSc + y)*NFFT;
  float2 v[8];
#pragma unroll
  for (int j=0;j<8;j++) v[j]=unpack(__ldcs(&src[j*32+t]));
  fft_inv(v,t);
  const float* bi = bias + ((size_t)lk*HSc + y)*HSc;
#pragma unroll
  for (int j=2;j<6;j++){
    int x = (j-2)*32 + t;
    float sb = spb(bi[x]);
    sm0[k][x] = logf(v[j].x + sb + 1e-6f);
    sm1[k][x] = logf(v[j].y + sb + 1e-6f);
  }
  __syncthreads();
  if (tid < 128){
    float e=0.f;
#pragma unroll
    for (int kk=0;kk<8;kk++) e += sm0[kk][tid];
    g_energy128[(((size_t)l)*HSc+y)*HSc+tid]=e;
  } else {
    int x = tid-128;
    float e=0.f;
#pragma unroll
    for (int kk=0;kk<8;kk++) e += sm1[kk][x];
    g_energy128[(((size_t)(Lc+l))*HSc+y)*HSc+x]=e;
  }
}

// ---------------- upsample 128->512 + softmax stats ----------------
__global__ void k_u1(){
  int r = blockIdx.x;              // bl*128+y
  int X = threadIdx.x;
  int s0 = g_wU128s[X];
  const float* src = g_energy128 + (size_t)r*HSc;
  float acc=0.f;
#pragma unroll
  for (int j=0;j<4;j++){
    int i = min(max(s0+j,0),HSc-1);
    acc = fmaf(g_wU128T[j][X], src[i], acc);
  }
  g_tmpA[(size_t)r*HMc+X]=acc;
}
__global__ void k_u2(const float* __restrict__ heat){
  int rY = blockIdx.x;             // bl*512+Y
  int bl = rY>>9, Y = rY&511;
  int l = bl % Lc;
  int X = threadIdx.x;
  int s0 = g_wU128s[Y];
  float acc=0.f;
#pragma unroll
  for (int j=0;j<4;j++){
    int i = min(max(s0+j,0),HSc-1);
    acc = fmaf(g_wU128T[j][Y], g_tmpA[((size_t)bl*HSc+i)*HMc+X], acc);
  }
  float h = heat[(size_t)rY*HMc+X];
  float hm = fmaf(h, g_scale[l], g_bofs[l]);
  float e = acc + logf(spb(hm)+1e-6f);
  __shared__ float sh16[16];
  float m = bredmax(e, sh16);
  float p = __expf(e - m);
  float s = bredsum(p, sh16);
  float sx = bredsum(p*(float)X, sh16);
  if (!X) g_rs[rY]=make_float4(m, s, sx, 0.f);
}
__global__ void k_final(float* __restrict__ out){
  int bl=blockIdx.x, t=threadIdx.x;
  float4 v = g_rs[bl*HMc+t];
  __shared__ float sh16[16];
  float gmax = bredmax(v.x, sh16);
  float w = __expf(v.x - gmax);
  float s0 = bredsum(v.y*w, sh16);
  float s1 = bredsum(v.z*w, sh16);
  float s2 = bredsum((float)t*v.y*w, sh16);
  if (!t){
    out[bl*3+0]=1.f;
    out[bl*3+1]=s2/s0;
    out[bl*3+2]=s1/s0;
  }
}

extern "C" void kernel_launch(void* const* d_in, const int* in_sizes, int n_in,
                              void* d_out, int out_size){
  const float* heat  = (const float*)d_in[0];
  const float* cond  = (const float*)d_in[1];
  const float* bias  = (const float*)d_in[2];
  const float* gamma = (const float*)d_in[3];
  const float* beta  = (const float*)d_in[4];
  const int*   vidx  = (const int*)d_in[5];
  float* out = (float*)d_out;

  k_setup<<<1,512>>>();
  k_r1<<<NBL*HMc,128>>>(heat);
  k_bn_final<<<Lc,256>>>(gamma, beta);
  k_r2<<<NBL*HSc,128>>>();
  k_prior<<<NIMGP*HSc,128>>>(cond);
  k_rows<<<dim3(NIMGP*HSc/8,2),256>>>(vidx);
  k_cols_conv<<<dim3(32,NIMGP),256>>>();
  k_energy<<<Lc*HSc,256>>>(bias);
  k_u1<<<NBL*HSc,512>>>();
  k_u2<<<NBL*HMc,512>>>(heat);
  k_final<<<NBL,512>>>(out);
}